// round 8
// baseline (speedup 1.0000x reference)
#include <cuda_runtime.h>
#include <math.h>
#include <stdint.h>

// Problem constants (fixed by the reference)
#define BATCH 8
#define TT    4096
#define DD    768
#define HH    768
#define MM    (BATCH * TT)      // 32768 flattened rows
#define CHUNK 128
#define NC    (TT / CHUNK)      // 32 chunks

// Scratch (static device globals: allocation-free per harness rules)
__device__ float g_A [(size_t)MM * HH];   // a_t  = f'_t            (100.7 MB)
__device__ float g_Bv[(size_t)MM * HH];   // b_t  = i'_t * h~_t     (100.7 MB)
__device__ float g_aggA[BATCH * NC * HH]; // per-chunk prod(a)
__device__ float g_aggB[BATCH * NC * HH]; // per-chunk combined b
__device__ float g_pref[BATCH * NC * HH]; // h before each chunk

// ---------------------------------------------------------------------------
// Kernel 1: fused triple GEMM (tf32 tensor cores) + gate epilogue.
// Tile: BM=128 x BN=64 x BK=32. 8 warps laid out 4(m) x 2(n); each warp
// owns a 32x32 warp tile = 2(m16) x 4(n8) mma tiles, 3 projections.
// ---------------------------------------------------------------------------
#define BM 128
#define BN 64
#define BK 32
#define BKP 36   // padded smem stride -> conflict-free fragment loads

// cvt to tf32: destination MUST be .b32
__device__ __forceinline__ float tf32r(float f) {
    uint32_t u;
    asm("cvt.rna.tf32.f32 %0, %1;" : "=r"(u) : "f"(f));
    return __uint_as_float(u);
}

__device__ __forceinline__ void mma_tf32(float& c0, float& c1, float& c2, float& c3,
                                         uint32_t a0, uint32_t a1, uint32_t a2, uint32_t a3,
                                         uint32_t b0, uint32_t b1) {
    asm volatile(
        "mma.sync.aligned.m16n8k8.row.col.f32.tf32.tf32.f32 "
        "{%0,%1,%2,%3}, {%4,%5,%6,%7}, {%8,%9}, {%0,%1,%2,%3};\n"
        : "+f"(c0), "+f"(c1), "+f"(c2), "+f"(c3)
        : "r"(a0), "r"(a1), "r"(a2), "r"(a3), "r"(b0), "r"(b1));
}

__global__ __launch_bounds__(256, 1)
void gates_gemm_kernel(const float* __restrict__ x,
                       const float* __restrict__ fw, const float* __restrict__ fb,
                       const float* __restrict__ iw, const float* __restrict__ ib,
                       const float* __restrict__ hw, const float* __restrict__ hb)
{
    __shared__ float xs [BM * BKP];   // 128x36
    __shared__ float ws0[BN * BKP];   //  64x36
    __shared__ float ws1[BN * BKP];
    __shared__ float ws2[BN * BKP];

    const int tid = threadIdx.x;
    const int L   = tid & 31;
    const int w   = tid >> 5;
    const int wm  = w >> 1;          // 0..3 -> 32-row band
    const int wn  = w & 1;           // 0..1 -> 32-col band
    const int m0b = blockIdx.y * BM;
    const int n0b = blockIdx.x * BN;

    // global->smem load mapping
    // x tile: 128x32 = 1024 float4, 4 per thread (rows er+{0,32,64,96})
    // w tiles: 64x32 = 512 float4, 2 per thread each (rows er+{0,32})
    const int er  = tid >> 3;              // 0..31
    const int ec0 = (tid & 7) * 4;         // col

    // fragment lane decomposition
    const int fr = L >> 2;                 // 0..7
    const int fc = L & 3;                  // 0..3

    float cf[2][4][4] = {}, ci[2][4][4] = {}, ch[2][4][4] = {};
    float4 rx[4], rwf[2], rwi[2], rwh[2];

#define LOAD_REGS(K0)                                                          \
    {                                                                          \
        _Pragma("unroll")                                                      \
        for (int j = 0; j < 4; j++)                                            \
            rx[j] = *(const float4*)&x [(size_t)(m0b + er + j * 32) * DD + (K0) + ec0]; \
        _Pragma("unroll")                                                      \
        for (int j = 0; j < 2; j++) {                                          \
            size_t wrow = (size_t)(n0b + er + j * 32) * DD + (K0) + ec0;       \
            rwf[j] = *(const float4*)&fw[wrow];                                \
            rwi[j] = *(const float4*)&iw[wrow];                                \
            rwh[j] = *(const float4*)&hw[wrow];                                \
        }                                                                      \
    }

#define CVT4(V) { (V).x = tf32r((V).x); (V).y = tf32r((V).y); (V).z = tf32r((V).z); (V).w = tf32r((V).w); }

#define STORE_SMEM()                                                           \
    {                                                                          \
        _Pragma("unroll")                                                      \
        for (int j = 0; j < 4; j++) {                                          \
            CVT4(rx[j]);                                                       \
            *(float4*)&xs[(er + j * 32) * BKP + ec0] = rx[j];                  \
        }                                                                      \
        _Pragma("unroll")                                                      \
        for (int j = 0; j < 2; j++) {                                          \
            CVT4(rwf[j]); CVT4(rwi[j]); CVT4(rwh[j]);                          \
            *(float4*)&ws0[(er + j * 32) * BKP + ec0] = rwf[j];                \
            *(float4*)&ws1[(er + j * 32) * BKP + ec0] = rwi[j];                \
            *(float4*)&ws2[(er + j * 32) * BKP + ec0] = rwh[j];                \
        }                                                                      \
    }

#define COMPUTE()                                                              \
    {                                                                          \
        _Pragma("unroll")                                                      \
        for (int kk = 0; kk < BK; kk += 8) {                                   \
            uint32_t A[2][4];                                                  \
            _Pragma("unroll")                                                  \
            for (int mt = 0; mt < 2; mt++) {                                   \
                int mr = wm * 32 + mt * 16 + fr;                               \
                A[mt][0] = __float_as_uint(xs[(mr    ) * BKP + kk + fc    ]);  \
                A[mt][1] = __float_as_uint(xs[(mr + 8) * BKP + kk + fc    ]);  \
                A[mt][2] = __float_as_uint(xs[(mr    ) * BKP + kk + fc + 4]);  \
                A[mt][3] = __float_as_uint(xs[(mr + 8) * BKP + kk + fc + 4]);  \
            }                                                                  \
            _Pragma("unroll")                                                  \
            for (int nt = 0; nt < 4; nt++) {                                   \
                int nb = (wn * 32 + nt * 8 + (L >> 2)) * BKP + kk + (L & 3);   \
                uint32_t bf0 = __float_as_uint(ws0[nb]);                       \
                uint32_t bf1 = __float_as_uint(ws0[nb + 4]);                   \
                uint32_t bi0 = __float_as_uint(ws1[nb]);                       \
                uint32_t bi1 = __float_as_uint(ws1[nb + 4]);                   \
                uint32_t bh0 = __float_as_uint(ws2[nb]);                       \
                uint32_t bh1 = __float_as_uint(ws2[nb + 4]);                   \
                _Pragma("unroll")                                              \
                for (int mt = 0; mt < 2; mt++) {                               \
                    mma_tf32(cf[mt][nt][0], cf[mt][nt][1], cf[mt][nt][2], cf[mt][nt][3], \
                             A[mt][0], A[mt][1], A[mt][2], A[mt][3], bf0, bf1);\
                    mma_tf32(ci[mt][nt][0], ci[mt][nt][1], ci[mt][nt][2], ci[mt][nt][3], \
                             A[mt][0], A[mt][1], A[mt][2], A[mt][3], bi0, bi1);\
                    mma_tf32(ch[mt][nt][0], ch[mt][nt][1], ch[mt][nt][2], ch[mt][nt][3], \
                             A[mt][0], A[mt][1], A[mt][2], A[mt][3], bh0, bh1);\
                }                                                              \
            }                                                                  \
        }                                                                      \
    }

    // ---- pipeline: prefetch-to-regs double buffering ----
    LOAD_REGS(0);
    STORE_SMEM();
    __syncthreads();
    for (int k0 = BK; k0 < DD; k0 += BK) {
        LOAD_REGS(k0);
        COMPUTE();
        __syncthreads();
        STORE_SMEM();
        __syncthreads();
    }
    COMPUTE();

    // ---- epilogue: gates -> (a, b) scan coefficients ----
    #pragma unroll
    for (int mt = 0; mt < 2; mt++) {
        #pragma unroll
        for (int nt = 0; nt < 4; nt++) {
            int rbase = m0b + wm * 32 + mt * 16 + (L >> 2);
            int cbase = n0b + wn * 32 + nt * 8 + 2 * (L & 3);
            #pragma unroll
            for (int e = 0; e < 4; e++) {
                int m = rbase + ((e >> 1) ? 8 : 0);
                int h = cbase + (e & 1);
                float fv, iv, ht;
                if (0) {}
                fv = 1.0f / (1.0f + __expf(-(cf[mt][nt][e] + fb[h])));
                iv = 1.0f / (1.0f + __expf(-(ci[mt][nt][e] + ib[h])));
                ht = ch[mt][nt][e] + hb[h];
                float inv_den = 1.0f / (fv + iv + 1e-8f);
                size_t o = (size_t)m * HH + h;
                g_A [o] = fv * inv_den;
                g_Bv[o] = iv * inv_den * ht;
            }
        }
    }
#undef LOAD_REGS
#undef CVT4
#undef STORE_SMEM
#undef COMPUTE
}

// ---------------------------------------------------------------------------
// Kernel 2 (phase A): per-chunk affine aggregate.
// ---------------------------------------------------------------------------
__global__ void scan_phaseA_kernel()
{
    int idx = blockIdx.x * blockDim.x + threadIdx.x;  // < BATCH*NC*HH
    int h   = idx % HH;
    int rem = idx / HH;
    int c   = rem % NC;
    int b   = rem / NC;

    size_t base = ((size_t)b * TT + (size_t)c * CHUNK) * HH + h;
    float Ap = 1.0f, Bc = 0.0f;
    #pragma unroll 4
    for (int t = 0; t < CHUNK; t++) {
        float a  = g_A [base + (size_t)t * HH];
        float bb = g_Bv[base + (size_t)t * HH];
        Bc = fmaf(a, Bc, bb);
        Ap = Ap * a;
    }
    g_aggA[idx] = Ap;
    g_aggB[idx] = Bc;
}

// ---------------------------------------------------------------------------
// Kernel 3 (phase B): serial composition across chunks. Tiny.
// ---------------------------------------------------------------------------
__global__ void scan_phaseB_kernel(const float* __restrict__ h0)
{
    int idx = blockIdx.x * blockDim.x + threadIdx.x;  // < BATCH*HH
    int h = idx % HH;
    int b = idx / HH;

    float hp = h0[(size_t)b * HH + h];
    #pragma unroll
    for (int c = 0; c < NC; c++) {
        size_t ai = ((size_t)b * NC + c) * HH + h;
        g_pref[ai] = hp;
        hp = fmaf(g_aggA[ai], hp, g_aggB[ai]);
    }
}

// ---------------------------------------------------------------------------
// Kernel 4 (phase C): replay each chunk with its prefix, write h_t to out.
// ---------------------------------------------------------------------------
__global__ void scan_phaseC_kernel(float* __restrict__ out)
{
    int idx = blockIdx.x * blockDim.x + threadIdx.x;  // < BATCH*NC*HH
    int h   = idx % HH;
    int rem = idx / HH;
    int c   = rem % NC;
    int b   = rem / NC;

    size_t base = ((size_t)b * TT + (size_t)c * CHUNK) * HH + h;
    float hcur = g_pref[idx];
    #pragma unroll 4
    for (int t = 0; t < CHUNK; t++) {
        size_t o = base + (size_t)t * HH;
        hcur = fmaf(g_A[o], hcur, g_Bv[o]);
        out[o] = hcur;
    }
}

// ---------------------------------------------------------------------------
extern "C" void kernel_launch(void* const* d_in, const int* in_sizes, int n_in,
                              void* d_out, int out_size)
{
    const float* x  = (const float*)d_in[0];
    const float* h0 = (const float*)d_in[1];
    const float* fw = (const float*)d_in[2];
    const float* fb = (const float*)d_in[3];
    const float* iw = (const float*)d_in[4];
    const float* ib = (const float*)d_in[5];
    const float* hw = (const float*)d_in[6];
    const float* hb = (const float*)d_in[7];
    float* out = (float*)d_out;

    dim3 ggrid(HH / BN, MM / BM);     // (12, 256)
    gates_gemm_kernel<<<ggrid, 256>>>(x, fw, fb, iw, ib, hw, hb);

    scan_phaseA_kernel<<<(BATCH * NC * HH) / 256, 256>>>();
    scan_phaseB_kernel<<<(BATCH * HH) / 256, 256>>>(h0);
    scan_phaseC_kernel<<<(BATCH * NC * HH) / 256, 256>>>(out);
}

// round 10
// speedup vs baseline: 1.0427x; 1.0427x over previous
#include <cuda_runtime.h>
#include <math.h>
#include <stdint.h>

// Problem constants
#define BATCH 8
#define TT    4096
#define DD    768
#define HH    768
#define MM    (BATCH * TT)      // 32768 rows
#define CHUNK 128
#define NC    (TT / CHUNK)      // 32 chunks

// Scratch (static device globals)
__device__ float g_A [(size_t)MM * HH];
__device__ float g_Bv[(size_t)MM * HH];
__device__ float g_Xr[(size_t)MM * DD];        // tf32-rounded x (100.7 MB)
__device__ float g_Wr[(size_t)3 * HH * DD];    // tf32-rounded f/i/h weights (7 MB)
__device__ float g_aggA[BATCH * NC * HH];
__device__ float g_aggB[BATCH * NC * HH];
__device__ float g_pref[BATCH * NC * HH];

// ---------------------------------------------------------------------------
// GEMM config: BM=128 x BN=64 x BK=32, 256 threads, 8 warps (4m x 2n),
// warp tile 32x32 = 2(m16) x 4(n8) mma tiles x 3 projections.
// 4-stage cp.async pipeline on pre-rounded operands.
// ---------------------------------------------------------------------------
#define GBM 128
#define GBN 64
#define GBK 32
#define BKP 36                       // padded row (144 B, 16B-aligned)
#define STAGES 4
#define N_ITERS (DD / GBK)           // 24
#define XS_FLOATS (GBM * BKP)        // 4608
#define WS_FLOATS (GBN * BKP)        // 2304
#define STAGE_FLOATS (XS_FLOATS + 3 * WS_FLOATS)   // 11520
#define SMEM_BYTES (STAGES * STAGE_FLOATS * 4)     // 184320

__device__ __forceinline__ float tf32r(float f) {
    uint32_t u;
    asm("cvt.rna.tf32.f32 %0, %1;" : "=r"(u) : "f"(f));
    return __uint_as_float(u);
}
__device__ __forceinline__ uint32_t smem_u32(const void* p) {
    uint32_t a;
    asm("{ .reg .u64 t; cvta.to.shared.u64 t, %1; cvt.u32.u64 %0, t; }" : "=r"(a) : "l"(p));
    return a;
}
__device__ __forceinline__ void cp16(uint32_t d, const float* g) {
    uint64_t ga;
    asm("cvta.to.global.u64 %0, %1;" : "=l"(ga) : "l"(g));
    asm volatile("cp.async.cg.shared.global [%0], [%1], 16;" :: "r"(d), "l"(ga) : "memory");
}
__device__ __forceinline__ void mma_tf32(float& c0, float& c1, float& c2, float& c3,
                                         uint32_t a0, uint32_t a1, uint32_t a2, uint32_t a3,
                                         uint32_t b0, uint32_t b1) {
    asm volatile(
        "mma.sync.aligned.m16n8k8.row.col.f32.tf32.tf32.f32 "
        "{%0,%1,%2,%3}, {%4,%5,%6,%7}, {%8,%9}, {%0,%1,%2,%3};\n"
        : "+f"(c0), "+f"(c1), "+f"(c2), "+f"(c3)
        : "r"(a0), "r"(a1), "r"(a2), "r"(a3), "r"(b0), "r"(b1));
}

extern __shared__ float smf[];

__global__ __launch_bounds__(256, 1)
void gates_gemm_cp(const float* __restrict__ fb, const float* __restrict__ ib,
                   const float* __restrict__ hb)
{
    const int tid = threadIdx.x;
    const int L   = tid & 31;
    const int w   = tid >> 5;
    const int wm  = w >> 1;          // 0..3 -> 32-row band
    const int wn  = w & 1;           // 0..1 -> 32-col band
    const int m0b = blockIdx.y * GBM;
    const int n0b = blockIdx.x * GBN;

    // cp.async load mapping: xr in 0..31, xc word col
    const int xr = tid >> 3;
    const int xc = (tid & 7) * 4;

    const uint32_t s_u = smem_u32(smf);

    float cf[2][4][4] = {}, ci[2][4][4] = {}, ch[2][4][4] = {};

#define ISSUE_LOAD(ST, KB)                                                     \
    {                                                                          \
        uint32_t sb = s_u + (uint32_t)(ST) * (STAGE_FLOATS * 4);               \
        const float* gx = g_Xr + (size_t)(m0b + xr) * DD + (KB) * GBK + xc;    \
        _Pragma("unroll")                                                      \
        for (int j = 0; j < 4; j++)                                            \
            cp16(sb + ((xr + 32 * j) * BKP + xc) * 4, gx + (size_t)(32 * j) * DD); \
        _Pragma("unroll")                                                      \
        for (int p = 0; p < 3; p++) {                                          \
            const float* gw = g_Wr + (size_t)p * (HH * DD)                     \
                              + (size_t)(n0b + xr) * DD + (KB) * GBK + xc;     \
            uint32_t wb = sb + (XS_FLOATS + p * WS_FLOATS) * 4;                \
            _Pragma("unroll")                                                  \
            for (int j = 0; j < 2; j++)                                        \
                cp16(wb + ((xr + 32 * j) * BKP + xc) * 4, gw + (size_t)(32 * j) * DD); \
        }                                                                      \
    }

#define COMPUTE(ST)                                                            \
    {                                                                          \
        const float* xs  = smf + (ST) * STAGE_FLOATS;                          \
        const float* ws0 = xs + XS_FLOATS;                                     \
        const float* ws1 = ws0 + WS_FLOATS;                                    \
        const float* ws2 = ws1 + WS_FLOATS;                                    \
        const int fr = L >> 2, fc = L & 3;                                     \
        _Pragma("unroll")                                                      \
        for (int kk = 0; kk < GBK; kk += 8) {                                  \
            uint32_t A[2][4];                                                  \
            _Pragma("unroll")                                                  \
            for (int mt = 0; mt < 2; mt++) {                                   \
                int mr = wm * 32 + mt * 16 + fr;                               \
                A[mt][0] = __float_as_uint(xs[(mr    ) * BKP + kk + fc    ]);  \
                A[mt][1] = __float_as_uint(xs[(mr + 8) * BKP + kk + fc    ]);  \
                A[mt][2] = __float_as_uint(xs[(mr    ) * BKP + kk + fc + 4]);  \
                A[mt][3] = __float_as_uint(xs[(mr + 8) * BKP + kk + fc + 4]);  \
            }                                                                  \
            _Pragma("unroll")                                                  \
            for (int nt = 0; nt < 4; nt++) {                                   \
                int nb = (wn * 32 + nt * 8 + fr) * BKP + kk + fc;              \
                uint32_t bf0 = __float_as_uint(ws0[nb]);                       \
                uint32_t bf1 = __float_as_uint(ws0[nb + 4]);                   \
                uint32_t bi0 = __float_as_uint(ws1[nb]);                       \
                uint32_t bi1 = __float_as_uint(ws1[nb + 4]);                   \
                uint32_t bh0 = __float_as_uint(ws2[nb]);                       \
                uint32_t bh1 = __float_as_uint(ws2[nb + 4]);                   \
                _Pragma("unroll")                                              \
                for (int mt = 0; mt < 2; mt++) {                               \
                    mma_tf32(cf[mt][nt][0], cf[mt][nt][1], cf[mt][nt][2], cf[mt][nt][3], \
                             A[mt][0], A[mt][1], A[mt][2], A[mt][3], bf0, bf1);\
                    mma_tf32(ci[mt][nt][0], ci[mt][nt][1], ci[mt][nt][2], ci[mt][nt][3], \
                             A[mt][0], A[mt][1], A[mt][2], A[mt][3], bi0, bi1);\
                    mma_tf32(ch[mt][nt][0], ch[mt][nt][1], ch[mt][nt][2], ch[mt][nt][3], \
                             A[mt][0], A[mt][1], A[mt][2], A[mt][3], bh0, bh1);\
                }                                                              \
            }                                                                  \
        }                                                                      \
    }

    // ---- prologue: fill STAGES-1 stages ----
    #pragma unroll
    for (int s = 0; s < STAGES - 1; s++) {
        ISSUE_LOAD(s, s);
        asm volatile("cp.async.commit_group;" ::: "memory");
    }

    // ---- mainloop: one sync per iter, loads STAGES-1 ahead ----
    for (int it = 0; it < N_ITERS; it++) {
        asm volatile("cp.async.wait_group %0;" :: "n"(STAGES - 2) : "memory");
        __syncthreads();
        int nk = it + STAGES - 1;
        if (nk < N_ITERS) { ISSUE_LOAD(nk & (STAGES - 1), nk); }
        asm volatile("cp.async.commit_group;" ::: "memory");
        COMPUTE(it & (STAGES - 1));
    }

    // ---- epilogue ----
    #pragma unroll
    for (int mt = 0; mt < 2; mt++) {
        #pragma unroll
        for (int nt = 0; nt < 4; nt++) {
            int rbase = m0b + wm * 32 + mt * 16 + (L >> 2);
            int cbase = n0b + wn * 32 + nt * 8 + 2 * (L & 3);
            #pragma unroll
            for (int e = 0; e < 4; e++) {
                int m = rbase + ((e >> 1) ? 8 : 0);
                int h = cbase + (e & 1);
                float fv = 1.0f / (1.0f + __expf(-(cf[mt][nt][e] + fb[h])));
                float iv = 1.0f / (1.0f + __expf(-(ci[mt][nt][e] + ib[h])));
                float ht = ch[mt][nt][e] + hb[h];
                float inv_den = 1.0f / (fv + iv + 1e-8f);
                size_t o = (size_t)m * HH + h;
                g_A [o] = fv * inv_den;
                g_Bv[o] = iv * inv_den * ht;
            }
        }
    }
#undef ISSUE_LOAD
#undef COMPUTE
}

// ---------------------------------------------------------------------------
// Prep: pre-round x and weights to tf32 (cvt.rna) into scratch
// ---------------------------------------------------------------------------
__global__ void round_x_kernel(const float* __restrict__ x)
{
    size_t i = ((size_t)blockIdx.x * blockDim.x + threadIdx.x) * 4;
    float4 v = *(const float4*)&x[i];
    v.x = tf32r(v.x); v.y = tf32r(v.y); v.z = tf32r(v.z); v.w = tf32r(v.w);
    *(float4*)&g_Xr[i] = v;
}

__global__ void round_w_kernel(const float* __restrict__ fw,
                               const float* __restrict__ iw,
                               const float* __restrict__ hw)
{
    size_t i = ((size_t)blockIdx.x * blockDim.x + threadIdx.x) * 4;
    float4 v;
    v = *(const float4*)&fw[i];
    v.x = tf32r(v.x); v.y = tf32r(v.y); v.z = tf32r(v.z); v.w = tf32r(v.w);
    *(float4*)&g_Wr[i] = v;
    v = *(const float4*)&iw[i];
    v.x = tf32r(v.x); v.y = tf32r(v.y); v.z = tf32r(v.z); v.w = tf32r(v.w);
    *(float4*)&g_Wr[(size_t)HH * DD + i] = v;
    v = *(const float4*)&hw[i];
    v.x = tf32r(v.x); v.y = tf32r(v.y); v.z = tf32r(v.z); v.w = tf32r(v.w);
    *(float4*)&g_Wr[(size_t)2 * HH * DD + i] = v;
}

// ---------------------------------------------------------------------------
// scan phases (unchanged; near HBM roofline)
// ---------------------------------------------------------------------------
__global__ void scan_phaseA_kernel()
{
    int idx = blockIdx.x * blockDim.x + threadIdx.x;
    int h   = idx % HH;
    int rem = idx / HH;
    int c   = rem % NC;
    int b   = rem / NC;

    size_t base = ((size_t)b * TT + (size_t)c * CHUNK) * HH + h;
    float Ap = 1.0f, Bc = 0.0f;
    #pragma unroll 4
    for (int t = 0; t < CHUNK; t++) {
        float a  = g_A [base + (size_t)t * HH];
        float bb = g_Bv[base + (size_t)t * HH];
        Bc = fmaf(a, Bc, bb);
        Ap = Ap * a;
    }
    g_aggA[idx] = Ap;
    g_aggB[idx] = Bc;
}

__global__ void scan_phaseB_kernel(const float* __restrict__ h0)
{
    int idx = blockIdx.x * blockDim.x + threadIdx.x;
    int h = idx % HH;
    int b = idx / HH;

    float hp = h0[(size_t)b * HH + h];
    #pragma unroll
    for (int c = 0; c < NC; c++) {
        size_t ai = ((size_t)b * NC + c) * HH + h;
        g_pref[ai] = hp;
        hp = fmaf(g_aggA[ai], hp, g_aggB[ai]);
    }
}

__global__ void scan_phaseC_kernel(float* __restrict__ out)
{
    int idx = blockIdx.x * blockDim.x + threadIdx.x;
    int h   = idx % HH;
    int rem = idx / HH;
    int c   = rem % NC;
    int b   = rem / NC;

    size_t base = ((size_t)b * TT + (size_t)c * CHUNK) * HH + h;
    float hcur = g_pref[idx];
    #pragma unroll 4
    for (int t = 0; t < CHUNK; t++) {
        size_t o = base + (size_t)t * HH;
        hcur = fmaf(g_A[o], hcur, g_Bv[o]);
        out[o] = hcur;
    }
}

// ---------------------------------------------------------------------------
extern "C" void kernel_launch(void* const* d_in, const int* in_sizes, int n_in,
                              void* d_out, int out_size)
{
    const float* x  = (const float*)d_in[0];
    const float* h0 = (const float*)d_in[1];
    const float* fw = (const float*)d_in[2];
    const float* fb = (const float*)d_in[3];
    const float* iw = (const float*)d_in[4];
    const float* ib = (const float*)d_in[5];
    const float* hw = (const float*)d_in[6];
    const float* hb = (const float*)d_in[7];
    float* out = (float*)d_out;

    cudaFuncSetAttribute(gates_gemm_cp,
                         cudaFuncAttributeMaxDynamicSharedMemorySize, SMEM_BYTES);

    // prep: tf32-round operands into scratch
    round_x_kernel<<<(MM * DD / 4) / 256, 256>>>(x);
    round_w_kernel<<<(HH * DD / 4) / 256, 256>>>(fw, iw, hw);

    // triple GEMM + gate epilogue
    dim3 ggrid(HH / GBN, MM / GBM);   // (12, 256)
    gates_gemm_cp<<<ggrid, 256, SMEM_BYTES>>>(fb, ib, hb);

    // scans
    scan_phaseA_kernel<<<(BATCH * NC * HH) / 256, 256>>>();
    scan_phaseB_kernel<<<(BATCH * HH) / 256, 256>>>(h0);
    scan_phaseC_kernel<<<(BATCH * NC * HH) / 256, 256>>>(out);
}

// round 11
// speedup vs baseline: 1.2430x; 1.1921x over previous
#include <cuda_runtime.h>
#include <math.h>
#include <stdint.h>

// Problem constants
#define BATCH 8
#define TT    4096
#define DD    768
#define HH    768
#define MM    (BATCH * TT)      // 32768 rows
#define CHUNK 128
#define NC    (TT / CHUNK)      // 32 chunks

#define NKB   (DD / 8)          // 96 k8 blocks
#define NMB   (MM / 16)         // 2048 m16 blocks
#define NNB   (HH / 8)          // 96 n8 blocks

// Scratch (static device globals)
__device__ float g_A [(size_t)MM * HH];
__device__ float g_Bv[(size_t)MM * HH];
__device__ float g_Xf[(size_t)MM * DD];        // fragment-major tf32 x
__device__ float g_Wf[(size_t)3 * HH * DD];    // fragment-major tf32 weights
__device__ float g_aggA[BATCH * NC * HH];
__device__ float g_aggB[BATCH * NC * HH];
__device__ float g_pref[BATCH * NC * HH];

// ---------------------------------------------------------------------------
// GEMM: BM=64 x BN=64 x BK=32, 256 threads, 8 warps (2m x 4n), warp tile
// 32x16 = 2(m16) x 2(n8) mma tiles x 3 projections. 3-stage cp.async on
// fragment-major operands: A frag = 1 LDS.128, B frag = 1 LDS.64.
// ---------------------------------------------------------------------------
#define GBM 64
#define GBN 64
#define STAGES 3
#define N_ITERS (DD / 32)            // 24 iterations of 4 k8-blocks
#define A_STG_FLOATS 2048            // 4 m16 x 4 k8 x 128
#define B_STG_FLOATS 2048            // 8 n8  x 4 k8 x 64, per projection
#define STAGE_FLOATS (A_STG_FLOATS + 3 * B_STG_FLOATS)   // 8192 (32 KB)
#define SMEM_BYTES (STAGES * STAGE_FLOATS * 4)           // 98304

__device__ __forceinline__ float tf32r(float f) {
    uint32_t u;
    asm("cvt.rna.tf32.f32 %0, %1;" : "=r"(u) : "f"(f));
    return __uint_as_float(u);
}
__device__ __forceinline__ uint32_t smem_u32(const void* p) {
    uint32_t a;
    asm("{ .reg .u64 t; cvta.to.shared.u64 t, %1; cvt.u32.u64 %0, t; }" : "=r"(a) : "l"(p));
    return a;
}
__device__ __forceinline__ void cp16(uint32_t d, const float* g) {
    uint64_t ga;
    asm("cvta.to.global.u64 %0, %1;" : "=l"(ga) : "l"(g));
    asm volatile("cp.async.cg.shared.global [%0], [%1], 16;" :: "r"(d), "l"(ga) : "memory");
}
__device__ __forceinline__ void mma_tf32(float& c0, float& c1, float& c2, float& c3,
                                         uint32_t a0, uint32_t a1, uint32_t a2, uint32_t a3,
                                         uint32_t b0, uint32_t b1) {
    asm volatile(
        "mma.sync.aligned.m16n8k8.row.col.f32.tf32.tf32.f32 "
        "{%0,%1,%2,%3}, {%4,%5,%6,%7}, {%8,%9}, {%0,%1,%2,%3};\n"
        : "+f"(c0), "+f"(c1), "+f"(c2), "+f"(c3)
        : "r"(a0), "r"(a1), "r"(a2), "r"(a3), "r"(b0), "r"(b1));
}

extern __shared__ float smf[];

__global__ __launch_bounds__(256, 2)
void gates_gemm_fm(const float* __restrict__ fb, const float* __restrict__ ib,
                   const float* __restrict__ hb)
{
    const int tid = threadIdx.x;
    const int L   = tid & 31;
    const int w   = tid >> 5;
    const int wm  = w >> 2;          // 0..1 -> 32-row band
    const int wn  = w & 3;           // 0..3 -> 16-col band
    const int m0b = blockIdx.y * GBM;
    const int n0b = blockIdx.x * GBN;
    const int mb0 = blockIdx.y * 4;  // first m16 block
    const int nb0 = blockIdx.x * 8;  // first n8 block

    const uint32_t s_u = smem_u32(smf);

    float cf[2][2][4] = {}, ci[2][2][4] = {}, ch[2][2][4] = {};

    // Stage fill: pure linear copies (fragment-major global layout).
    // A: 4 segments of 2KB (one per m16 block, 4 contiguous k8 blocks).
    // B: per proj, 8 segments of 1KB (one per n8 block).
#define ISSUE_LOAD(ST, IT)                                                     \
    {                                                                          \
        uint32_t sb = s_u + (uint32_t)(ST) * (STAGE_FLOATS * 4);               \
        const int kb0 = (IT) * 4;                                              \
        _Pragma("unroll")                                                      \
        for (int i = 0; i < 2; i++) {                                          \
            int chunk = tid + i * 256;           /* 0..511, 16B each */        \
            int seg = chunk >> 7, within = chunk & 127;                        \
            const float* gs = g_Xf + (((size_t)(mb0 + seg) * NKB + kb0) * 128) \
                              + within * 4;                                    \
            cp16(sb + chunk * 16, gs);                                         \
        }                                                                      \
        _Pragma("unroll")                                                      \
        for (int p = 0; p < 3; p++) {                                          \
            uint32_t bb = sb + (A_STG_FLOATS + p * B_STG_FLOATS) * 4;          \
            _Pragma("unroll")                                                  \
            for (int i = 0; i < 2; i++) {                                      \
                int chunk = tid + i * 256;                                     \
                int seg = chunk >> 6, within = chunk & 63;                     \
                const float* gs = g_Wf +                                       \
                    (((size_t)(p * NNB + nb0 + seg) * NKB + kb0) * 64)         \
                    + within * 4;                                              \
                cp16(bb + chunk * 16, gs);                                     \
            }                                                                  \
        }                                                                      \
    }

#define COMPUTE(ST)                                                            \
    {                                                                          \
        const float* sA  = smf + (ST) * STAGE_FLOATS;                          \
        const float* sB0 = sA + A_STG_FLOATS;                                  \
        const float* sB1 = sB0 + B_STG_FLOATS;                                 \
        const float* sB2 = sB1 + B_STG_FLOATS;                                 \
        _Pragma("unroll")                                                      \
        for (int kb4 = 0; kb4 < 4; kb4++) {                                    \
            uint32_t A[2][4];                                                  \
            _Pragma("unroll")                                                  \
            for (int mt = 0; mt < 2; mt++) {                                   \
                int mb4 = wm * 2 + mt;                                         \
                float4 av = *(const float4*)&sA[(mb4 * 4 + kb4) * 128 + L * 4];\
                A[mt][0] = __float_as_uint(av.x);                              \
                A[mt][1] = __float_as_uint(av.y);                              \
                A[mt][2] = __float_as_uint(av.z);                              \
                A[mt][3] = __float_as_uint(av.w);                              \
            }                                                                  \
            _Pragma("unroll")                                                  \
            for (int nt = 0; nt < 2; nt++) {                                   \
                int off = ((wn * 2 + nt) * 4 + kb4) * 64 + L * 2;              \
                float2 vf = *(const float2*)&sB0[off];                         \
                float2 vi = *(const float2*)&sB1[off];                         \
                float2 vh = *(const float2*)&sB2[off];                         \
                _Pragma("unroll")                                              \
                for (int mt = 0; mt < 2; mt++) {                               \
                    mma_tf32(cf[mt][nt][0], cf[mt][nt][1], cf[mt][nt][2], cf[mt][nt][3], \
                             A[mt][0], A[mt][1], A[mt][2], A[mt][3],           \
                             __float_as_uint(vf.x), __float_as_uint(vf.y));    \
                    mma_tf32(ci[mt][nt][0], ci[mt][nt][1], ci[mt][nt][2], ci[mt][nt][3], \
                             A[mt][0], A[mt][1], A[mt][2], A[mt][3],           \
                             __float_as_uint(vi.x), __float_as_uint(vi.y));    \
                    mma_tf32(ch[mt][nt][0], ch[mt][nt][1], ch[mt][nt][2], ch[mt][nt][3], \
                             A[mt][0], A[mt][1], A[mt][2], A[mt][3],           \
                             __float_as_uint(vh.x), __float_as_uint(vh.y));    \
                }                                                              \
            }                                                                  \
        }                                                                      \
    }

    // ---- prologue: fill 2 stages ----
    ISSUE_LOAD(0, 0);
    asm volatile("cp.async.commit_group;" ::: "memory");
    ISSUE_LOAD(1, 1);
    asm volatile("cp.async.commit_group;" ::: "memory");

    // ---- mainloop ----
    int st = 0, nst = 2;
    for (int it = 0; it < N_ITERS; it++) {
        asm volatile("cp.async.wait_group %0;" :: "n"(STAGES - 2) : "memory");
        __syncthreads();
        int nk = it + STAGES - 1;
        if (nk < N_ITERS) { ISSUE_LOAD(nst, nk); }
        asm volatile("cp.async.commit_group;" ::: "memory");
        COMPUTE(st);
        st = (st + 1 == STAGES) ? 0 : st + 1;
        nst = (nst + 1 == STAGES) ? 0 : nst + 1;
    }

    // ---- epilogue: gates -> (a, b) scan coefficients ----
    #pragma unroll
    for (int mt = 0; mt < 2; mt++) {
        #pragma unroll
        for (int nt = 0; nt < 2; nt++) {
            int rbase = m0b + wm * 32 + mt * 16 + (L >> 2);
            int cbase = n0b + wn * 16 + nt * 8 + 2 * (L & 3);
            #pragma unroll
            for (int e = 0; e < 4; e++) {
                int m = rbase + ((e >> 1) ? 8 : 0);
                int h = cbase + (e & 1);
                float fv = 1.0f / (1.0f + __expf(-(cf[mt][nt][e] + fb[h])));
                float iv = 1.0f / (1.0f + __expf(-(ci[mt][nt][e] + ib[h])));
                float ht = ch[mt][nt][e] + hb[h];
                float inv_den = 1.0f / (fv + iv + 1e-8f);
                size_t o = (size_t)m * HH + h;
                g_A [o] = fv * inv_den;
                g_Bv[o] = iv * inv_den * ht;
            }
        }
    }
#undef ISSUE_LOAD
#undef COMPUTE
}

// ---------------------------------------------------------------------------
// Prep: permute + tf32-round operands into fragment-major scratch.
// x: [m16 block][k8 block][lane] float4 = {x[r,c], x[r+8,c], x[r,c+4], x[r+8,c+4]}
//    r = mb*16 + L>>2, c = kb*8 + L&3
// ---------------------------------------------------------------------------
__global__ void permute_x_kernel(const float* __restrict__ x)
{
    int idx = blockIdx.x * blockDim.x + threadIdx.x;   // < NMB*NKB*32
    int L  = idx & 31;
    int kb = (idx >> 5) % NKB;
    int mb = (idx >> 5) / NKB;
    int r = mb * 16 + (L >> 2);
    int c = kb * 8 + (L & 3);
    float4 v;
    v.x = tf32r(x[(size_t)r * DD + c]);
    v.y = tf32r(x[(size_t)(r + 8) * DD + c]);
    v.z = tf32r(x[(size_t)r * DD + c + 4]);
    v.w = tf32r(x[(size_t)(r + 8) * DD + c + 4]);
    *(float4*)&g_Xf[(size_t)idx * 4] = v;
}

// W: [proj][n8 block][k8 block][lane] float2 = {W[n,k], W[n,k+4]}
//    n = nb*8 + L>>2, k = kb*8 + L&3
__global__ void permute_w_kernel(const float* __restrict__ fw,
                                 const float* __restrict__ iw,
                                 const float* __restrict__ hw)
{
    int idx = blockIdx.x * blockDim.x + threadIdx.x;   // < 3*NNB*NKB*32
    int L  = idx & 31;
    int kb = (idx >> 5) % NKB;
    int nb = ((idx >> 5) / NKB) % NNB;
    int p  = (idx >> 5) / (NKB * NNB);
    int n = nb * 8 + (L >> 2);
    int k = kb * 8 + (L & 3);
    const float* W = (p == 0) ? fw : (p == 1) ? iw : hw;
    float2 v;
    v.x = tf32r(W[(size_t)n * DD + k]);
    v.y = tf32r(W[(size_t)n * DD + k + 4]);
    *(float2*)&g_Wf[(size_t)idx * 2] = v;
}

// ---------------------------------------------------------------------------
// scan phases (unchanged; near HBM roofline)
// ---------------------------------------------------------------------------
__global__ void scan_phaseA_kernel()
{
    int idx = blockIdx.x * blockDim.x + threadIdx.x;
    int h   = idx % HH;
    int rem = idx / HH;
    int c   = rem % NC;
    int b   = rem / NC;

    size_t base = ((size_t)b * TT + (size_t)c * CHUNK) * HH + h;
    float Ap = 1.0f, Bc = 0.0f;
    #pragma unroll 4
    for (int t = 0; t < CHUNK; t++) {
        float a  = g_A [base + (size_t)t * HH];
        float bb = g_Bv[base + (size_t)t * HH];
        Bc = fmaf(a, Bc, bb);
        Ap = Ap * a;
    }
    g_aggA[idx] = Ap;
    g_aggB[idx] = Bc;
}

__global__ void scan_phaseB_kernel(const float* __restrict__ h0)
{
    int idx = blockIdx.x * blockDim.x + threadIdx.x;
    int h = idx % HH;
    int b = idx / HH;

    float hp = h0[(size_t)b * HH + h];
    #pragma unroll
    for (int c = 0; c < NC; c++) {
        size_t ai = ((size_t)b * NC + c) * HH + h;
        g_pref[ai] = hp;
        hp = fmaf(g_aggA[ai], hp, g_aggB[ai]);
    }
}

__global__ void scan_phaseC_kernel(float* __restrict__ out)
{
    int idx = blockIdx.x * blockDim.x + threadIdx.x;
    int h   = idx % HH;
    int rem = idx / HH;
    int c   = rem % NC;
    int b   = rem / NC;

    size_t base = ((size_t)b * TT + (size_t)c * CHUNK) * HH + h;
    float hcur = g_pref[idx];
    #pragma unroll 4
    for (int t = 0; t < CHUNK; t++) {
        size_t o = base + (size_t)t * HH;
        hcur = fmaf(g_A[o], hcur, g_Bv[o]);
        out[o] = hcur;
    }
}

// ---------------------------------------------------------------------------
extern "C" void kernel_launch(void* const* d_in, const int* in_sizes, int n_in,
                              void* d_out, int out_size)
{
    const float* x  = (const float*)d_in[0];
    const float* h0 = (const float*)d_in[1];
    const float* fw = (const float*)d_in[2];
    const float* fb = (const float*)d_in[3];
    const float* iw = (const float*)d_in[4];
    const float* ib = (const float*)d_in[5];
    const float* hw = (const float*)d_in[6];
    const float* hb = (const float*)d_in[7];
    float* out = (float*)d_out;

    cudaFuncSetAttribute(gates_gemm_fm,
                         cudaFuncAttributeMaxDynamicSharedMemorySize, SMEM_BYTES);

    // prep: fragment-major tf32 operands
    permute_x_kernel<<<(NMB * NKB * 32) / 256, 256>>>(x);
    permute_w_kernel<<<(3 * NNB * NKB * 32) / 256, 256>>>(fw, iw, hw);

    // triple GEMM + gate epilogue
    dim3 ggrid(HH / GBN, MM / GBM);   // (12, 512)
    gates_gemm_fm<<<ggrid, 256, SMEM_BYTES>>>(fb, ib, hb);

    // scans
    scan_phaseA_kernel<<<(BATCH * NC * HH) / 256, 256>>>();
    scan_phaseB_kernel<<<(BATCH * HH) / 256, 256>>>(h0);
    scan_phaseC_kernel<<<(BATCH * NC * HH) / 256, 256>>>(out);
}